// round 6
// baseline (speedup 1.0000x reference)
#include <cuda_runtime.h>
#include <cstdint>

// SM-2 scan: f32x2 packed, predicate-carried, fma-pipe-balanced selects.
// hist_p: [B, 400] f32. Block = 128 threads = 4 warps; warp owns 64 rows
// (lane -> rows lane, lane+32). Double-buffered warp-private smem tiles.
//
// Step reformulation (output-exact vs reference):
//   R = I a correct answer would yield next step.  R==1 <=> prev incorrect,
//   so the R==1 test is replaced by the carried previous-step predicate.
//   I = correct ? R : 1  and  R = correct ? (prev ? I*EF : 6) : 1 are computed
//   as fma(m, x-1, 1) with float mask m (exact select; x-1 exact or x>=2^24
//   where -1/+1 round back to x). R is clamped to 274 once per chunk: keeps
//   all operands finite (no 0*inf NaN) and provably preserves the final
//   output (mid-run min commutes with the deferred output clamp).

static constexpr int STEPS          = 400;
static constexpr int RPW            = 64;
static constexpr int WARPS          = 4;
static constexpr int THREADS        = 32 * WARPS;          // 128
static constexpr int ROWS_PER_BLOCK = RPW * WARPS;         // 256
static constexpr int CHUNK          = 16;
static constexpr int NCHUNK         = STEPS / CHUNK;       // 25 exact
static constexpr int STRIDE         = CHUNK + 4;           // 20: conflict-free LDS.128
static constexpr int WBUF           = RPW * STRIDE;        // 1280 floats
static constexpr int SMEM_BYTES     = WARPS * 2 * WBUF * (int)sizeof(float); // 40960

__device__ __forceinline__ uint32_t smem_u32(const void* p) {
    return (uint32_t)__cvta_generic_to_shared(p);
}
__device__ __forceinline__ void cp_async16(uint32_t saddr, const void* gptr) {
    asm volatile("cp.async.cg.shared.global [%0], [%1], 16;\n" :: "r"(saddr), "l"(gptr));
}
__device__ __forceinline__ void cp_commit() {
    asm volatile("cp.async.commit_group;\n" ::: "memory");
}
template <int N>
__device__ __forceinline__ void cp_wait() {
    asm volatile("cp.async.wait_group %0;\n" :: "n"(N) : "memory");
}

// Packed f32x2 helpers (sm_103a FADD2/FMUL2/FFMA2 via PTX).
union F2 { float f[2]; unsigned long long u; };
__device__ __forceinline__ F2 mk2(float a, float b) { F2 r; r.f[0] = a; r.f[1] = b; return r; }
__device__ __forceinline__ F2 mul2(F2 a, F2 b) {
    F2 d; asm("mul.rn.f32x2 %0, %1, %2;" : "=l"(d.u) : "l"(a.u), "l"(b.u)); return d;
}
__device__ __forceinline__ F2 add2(F2 a, F2 b) {
    F2 d; asm("add.rn.f32x2 %0, %1, %2;" : "=l"(d.u) : "l"(a.u), "l"(b.u)); return d;
}
__device__ __forceinline__ F2 fma2(F2 a, F2 b, F2 c) {
    F2 d; asm("fma.rn.f32x2 %0, %1, %2, %3;" : "=l"(d.u) : "l"(a.u), "l"(b.u), "l"(c.u)); return d;
}

// One step for two independent rows. qa/qb carry the previous step's predicate.
__device__ __forceinline__ void sm2_step2(float pa, float pb,
                                          F2& I, F2& EF, F2& R, bool& qa, bool& qb) {
    const bool ca = pa >= 0.6f;          // == (p*5 >= 3) in RN
    const bool cb = pb >= 0.6f;

    F2 m;                                 // float mask, shared by I and R selects
    m.f[0] = ca ? 1.0f : 0.0f;
    m.f[1] = cb ? 1.0f : 0.0f;

    const F2 mone = mk2(-1.0f, -1.0f);
    const F2 one  = mk2( 1.0f,  1.0f);

    F2 Rm1 = add2(R, mone);
    I = fma2(m, Rm1, one);               // I = ca ? R : 1  (exact)

    F2 p = mk2(pa, pb);
    F2 w = fma2(p, mk2(-0.5f, -0.5f), mk2(1.4f, 1.4f));
    F2 u = fma2(p, w, mk2(-0.8f, -0.8f));   // 0.1-(5-5q/5)(...) polynomial
    F2 EFn = add2(EF, u);
    EFn.f[0] = fmaxf(EFn.f[0], 1.3f);
    EFn.f[1] = fmaxf(EFn.f[1], 1.3f);
    EF.f[0] = ca ? EFn.f[0] : EF.f[0];
    EF.f[1] = cb ? EFn.f[1] : EF.f[1];

    F2 t = mul2(I, EF);                  // I*EF with next step's entry values
    F2 X;                                // X = prev-correct ? t : 6
    X.f[0] = qa ? t.f[0] : 6.0f;
    X.f[1] = qb ? t.f[1] : 6.0f;
    F2 Xm1 = add2(X, mone);
    R = fma2(m, Xm1, one);               // R = ca ? X : 1  (exact; X finite)

    qa = ca; qb = cb;
}

extern __shared__ float sbuf[];

__global__ void __launch_bounds__(THREADS, 5)
sm2_scan_kernel(const float* __restrict__ hist, float* __restrict__ out, int B) {
    const int lane  = threadIdx.x & 31;
    const int warp  = threadIdx.x >> 5;
    const int wrow0 = blockIdx.x * ROWS_PER_BLOCK + warp * RPW;

    float* buf0 = sbuf + warp * (2 * WBUF);
    float* buf1 = buf0 + WBUF;

    const float* g = hist + (size_t)wrow0 * STEPS;
    const bool full = (wrow0 + RPW <= B);

    auto load_chunk = [&](float* buf, int c0) {
        #pragma unroll
        for (int s = 0; s < 8; s++) {
            int f = s * 32 + lane;
            int r = f >> 2, k = f & 3;
            if (full || wrow0 + r < B)
                cp_async16(smem_u32(buf + r * STRIDE + k * 4),
                           g + (size_t)r * STEPS + c0 + k * 4);
        }
    };

    F2 I  = mk2(1.0f, 1.0f);
    F2 EF = mk2(2.5f, 2.5f);
    F2 R  = mk2(1.0f, 1.0f);
    bool qa = false, qb = false;         // R==1 at start <=> "prev incorrect"

    load_chunk(buf0, 0);
    cp_commit();

    const int ra = lane, rb = lane + 32;
    const bool livea = full || (wrow0 + ra < B);
    const bool liveb = full || (wrow0 + rb < B);

    #pragma unroll 1
    for (int c = 0; c < NCHUNK; c++) {
        float* cur = (c & 1) ? buf1 : buf0;
        float* nxt = (c & 1) ? buf0 : buf1;
        if (c + 1 < NCHUNK) {
            load_chunk(nxt, (c + 1) * CHUNK);
            cp_commit();
            cp_wait<1>();
        } else {
            cp_wait<0>();
        }
        __syncwarp();

        const float* ma = cur + ra * STRIDE;
        const float* mb = cur + rb * STRIDE;
        #pragma unroll
        for (int j = 0; j < CHUNK / 4; j++) {
            float4 va = *reinterpret_cast<const float4*>(ma + 4 * j);
            float4 vb = *reinterpret_cast<const float4*>(mb + 4 * j);
            sm2_step2(va.x, vb.x, I, EF, R, qa, qb);
            sm2_step2(va.y, vb.y, I, EF, R, qa, qb);
            sm2_step2(va.z, vb.z, I, EF, R, qa, qb);
            sm2_step2(va.w, vb.w, I, EF, R, qa, qb);
        }

        // Per-chunk clamp: keeps R finite within the next 16 steps
        // (274 * 42.5^16 < FLT_MAX) and is output-equivalent to the
        // reference's per-step clamp (min commutes along a surviving run).
        R.f[0] = fminf(R.f[0], 274.0f);
        R.f[1] = fminf(R.f[1], 274.0f);

        __syncwarp();
    }

    if (livea) out[wrow0 + ra] = fminf(I.f[0], 274.0f);
    if (liveb) out[wrow0 + rb] = fminf(I.f[1], 274.0f);
}

extern "C" void kernel_launch(void* const* d_in, const int* in_sizes, int n_in,
                              void* d_out, int out_size) {
    const float* hist = (const float*)d_in[0];
    float* out = (float*)d_out;
    int B = out_size;

    cudaFuncSetAttribute(sm2_scan_kernel,
                         cudaFuncAttributeMaxDynamicSharedMemorySize, SMEM_BYTES);

    int blocks = (B + ROWS_PER_BLOCK - 1) / ROWS_PER_BLOCK;
    sm2_scan_kernel<<<blocks, THREADS, SMEM_BYTES>>>(hist, out, B);
}

// round 7
// speedup vs baseline: 1.0511x; 1.0511x over previous
#include <cuda_runtime.h>
#include <cuda.h>
#include <cstdint>

// SM-2 scan: TMA-fed warp-private tiles + R5 packed-f32x2 step (2 rows/thread).
// hist_p: [B, 400] f32. Block = 128 threads = 4 warps; warp owns 64 rows
// (lane -> rows lane, lane+32). Each chunk (16 cols) arrives as ONE 2D TMA
// load per warp into a double-buffered 4KB tile (SW64 swizzle -> LDS.128
// conflict-free at 64B row pitch). mbarrier ring, parity (c>>1)&1.

static constexpr int STEPS          = 400;
static constexpr int RPW            = 64;
static constexpr int WARPS          = 4;
static constexpr int THREADS        = 32 * WARPS;           // 128
static constexpr int ROWS_PER_BLOCK = RPW * WARPS;          // 256
static constexpr int CHUNK          = 16;                   // floats per chunk
static constexpr int NCHUNK         = STEPS / CHUNK;        // 25 exact
static constexpr int TILE_BYTES     = RPW * CHUNK * 4;      // 4096

__device__ __forceinline__ uint32_t smem_u32(const void* p) {
    return (uint32_t)__cvta_generic_to_shared(p);
}
__device__ __forceinline__ void mbar_init(uint32_t mbar, uint32_t count) {
    asm volatile("mbarrier.init.shared.b64 [%0], %1;" :: "r"(mbar), "r"(count) : "memory");
}
__device__ __forceinline__ void mbar_expect_tx(uint32_t mbar, uint32_t bytes) {
    asm volatile("mbarrier.arrive.expect_tx.shared.b64 _, [%0], %1;"
                 :: "r"(mbar), "r"(bytes) : "memory");
}
__device__ __forceinline__ void mbar_wait(uint32_t mbar, uint32_t parity) {
    asm volatile(
        "{\n\t.reg .pred P;\n\t"
        "WL%=:\n\t"
        "mbarrier.try_wait.parity.shared::cta.b64 P, [%0], %1;\n\t"
        "@!P bra WL%=;\n\t}"
        :: "r"(mbar), "r"(parity) : "memory");
}
__device__ __forceinline__ void tma_load_2d(uint32_t dst, const CUtensorMap* map,
                                            int x, int y, uint32_t mbar) {
    asm volatile(
        "cp.async.bulk.tensor.2d.shared::cta.global.tile.mbarrier::complete_tx::bytes "
        "[%0], [%1, {%2, %3}], [%4];"
        :: "r"(dst), "l"(map), "r"(x), "r"(y), "r"(mbar) : "memory");
}

// Packed f32x2 helpers (sm_103a FFMA2/FMUL2 via PTX).
union F2 { float f[2]; unsigned long long u; };
__device__ __forceinline__ F2 mk2(float a, float b) { F2 r; r.f[0] = a; r.f[1] = b; return r; }
__device__ __forceinline__ F2 mul2(F2 a, F2 b) {
    F2 d; asm("mul.rn.f32x2 %0, %1, %2;" : "=l"(d.u) : "l"(a.u), "l"(b.u)); return d;
}
__device__ __forceinline__ F2 add2(F2 a, F2 b) {
    F2 d; asm("add.rn.f32x2 %0, %1, %2;" : "=l"(d.u) : "l"(a.u), "l"(b.u)); return d;
}
__device__ __forceinline__ F2 fma2(F2 a, F2 b, F2 c) {
    F2 d; asm("fma.rn.f32x2 %0, %1, %2, %3;" : "=l"(d.u) : "l"(a.u), "l"(b.u), "l"(c.u)); return d;
}

// R5 step (proven fastest formulation): R = I a correct answer yields next
// step; R==1 <=> prev incorrect (exact: product path >= 1.3). No per-step
// upper clamp (EF>=1.3 keeps product monotone in a run; clamp at output).
__device__ __forceinline__ void sm2_step2(float pa, float pb, F2& I, F2& EF, F2& R) {
    const bool ca = pa >= 0.6f;          // == (p*5 >= 3) in RN
    const bool cb = pb >= 0.6f;

    float Ia = ca ? R.f[0] : 1.0f;
    float Ib = cb ? R.f[1] : 1.0f;

    F2 p = mk2(pa, pb);
    F2 w = fma2(p, mk2(-0.5f, -0.5f), mk2(1.4f, 1.4f));
    F2 u = fma2(p, w, mk2(-0.8f, -0.8f));   // 0.1-(5-q)(0.08+(5-q)*0.02), q=5p
    F2 EFn = add2(EF, u);
    EFn.f[0] = fmaxf(EFn.f[0], 1.3f);
    EFn.f[1] = fmaxf(EFn.f[1], 1.3f);
    EF.f[0] = ca ? EFn.f[0] : EF.f[0];
    EF.f[1] = cb ? EFn.f[1] : EF.f[1];

    I = mk2(Ia, Ib);
    F2 t = mul2(I, EF);                  // I*EF with next step's entry values
    R.f[0] = ca ? ((R.f[0] == 1.0f) ? 6.0f : t.f[0]) : 1.0f;
    R.f[1] = cb ? ((R.f[1] == 1.0f) ? 6.0f : t.f[1]) : 1.0f;
}

__global__ void __launch_bounds__(THREADS, 6)
sm2_scan_kernel(const __grid_constant__ CUtensorMap tmap,
                float* __restrict__ out, int B) {
    __shared__ __align__(1024) float tiles[WARPS][2][RPW * CHUNK];  // 32 KB
    __shared__ __align__(8) unsigned long long mbar_store[WARPS][2];

    const int lane  = threadIdx.x & 31;
    const int warp  = threadIdx.x >> 5;
    const int wrow0 = blockIdx.x * ROWS_PER_BLOCK + warp * RPW;

    const uint32_t mb0 = smem_u32(&mbar_store[warp][0]);
    const uint32_t mb1 = smem_u32(&mbar_store[warp][1]);
    const uint32_t t0  = smem_u32(&tiles[warp][0][0]);
    const uint32_t t1  = smem_u32(&tiles[warp][1][0]);

    if (lane == 0) { mbar_init(mb0, 1); mbar_init(mb1, 1); }
    __syncwarp();

    // Prologue: chunk 0 into stage 0.
    if (lane == 0) {
        mbar_expect_tx(mb0, TILE_BYTES);
        tma_load_2d(t0, &tmap, 0, wrow0, mb0);
    }

    // Conflict-free SW64 read offsets: XOR term (8*lane)&0x30 is identical
    // for rows lane and lane+32 and for all j; per-j address = base ^ 16j.
    const uint32_t xo   = (8u * (uint32_t)lane) & 0x30u;
    const uint32_t offa = (64u * (uint32_t)lane) ^ xo;
    const uint32_t offb = offa + 2048u;      // row lane+32: +32*64B, same xor

    F2 I  = mk2(1.0f, 1.0f);
    F2 EF = mk2(2.5f, 2.5f);
    F2 R  = mk2(1.0f, 1.0f);

    const bool livea = (wrow0 + lane) < B;
    const bool liveb = (wrow0 + lane + 32) < B;

    #pragma unroll 1
    for (int c = 0; c < NCHUNK; c++) {
        const uint32_t cur_t  = (c & 1) ? t1 : t0;
        const uint32_t cur_mb = (c & 1) ? mb1 : mb0;

        if (c + 1 < NCHUNK && lane == 0) {
            const uint32_t nxt_t  = (c & 1) ? t0 : t1;
            const uint32_t nxt_mb = (c & 1) ? mb0 : mb1;
            mbar_expect_tx(nxt_mb, TILE_BYTES);
            tma_load_2d(nxt_t, &tmap, (c + 1) * CHUNK, wrow0, nxt_mb);
        }

        mbar_wait(cur_mb, (uint32_t)(c >> 1) & 1u);

        #pragma unroll
        for (int j = 0; j < CHUNK / 4; j++) {
            float4 va, vb;
            asm("ld.shared.v4.f32 {%0,%1,%2,%3}, [%4];"
                : "=f"(va.x), "=f"(va.y), "=f"(va.z), "=f"(va.w)
                : "r"(cur_t + (offa ^ (16u * j))));
            asm("ld.shared.v4.f32 {%0,%1,%2,%3}, [%4];"
                : "=f"(vb.x), "=f"(vb.y), "=f"(vb.z), "=f"(vb.w)
                : "r"(cur_t + (offb ^ (16u * j))));
            sm2_step2(va.x, vb.x, I, EF, R);
            sm2_step2(va.y, vb.y, I, EF, R);
            sm2_step2(va.z, vb.z, I, EF, R);
            sm2_step2(va.w, vb.w, I, EF, R);
        }
    }

    if (livea) out[wrow0 + lane]      = fminf(I.f[0], 274.0f);  // h_t = I
    if (liveb) out[wrow0 + lane + 32] = fminf(I.f[1], 274.0f);
}

// Host-side: cuTensorMapEncodeTiled via runtime entry-point lookup (no -lcuda).
typedef CUresult (*EncodeTiledFn)(
    CUtensorMap*, CUtensorMapDataType, cuuint32_t, void*,
    const cuuint64_t*, const cuuint64_t*, const cuuint32_t*, const cuuint32_t*,
    CUtensorMapInterleave, CUtensorMapSwizzle, CUtensorMapL2promotion,
    CUtensorMapFloatOOBfill);

extern "C" void kernel_launch(void* const* d_in, const int* in_sizes, int n_in,
                              void* d_out, int out_size) {
    const float* hist = (const float*)d_in[0];
    float* out = (float*)d_out;
    int B = out_size;

    void* fn = nullptr;
    cudaDriverEntryPointQueryResult qr;
    cudaGetDriverEntryPoint("cuTensorMapEncodeTiled", &fn, cudaEnableDefault, &qr);

    CUtensorMap tmap;
    cuuint64_t dims[2]    = {(cuuint64_t)STEPS, (cuuint64_t)B};
    cuuint64_t strides[1] = {(cuuint64_t)STEPS * sizeof(float)};
    cuuint32_t box[2]     = {(cuuint32_t)CHUNK, (cuuint32_t)RPW};
    cuuint32_t estr[2]    = {1, 1};
    ((EncodeTiledFn)fn)(&tmap, CU_TENSOR_MAP_DATA_TYPE_FLOAT32, 2, (void*)hist,
                        dims, strides, box, estr,
                        CU_TENSOR_MAP_INTERLEAVE_NONE, CU_TENSOR_MAP_SWIZZLE_64B,
                        CU_TENSOR_MAP_L2_PROMOTION_L2_128B,
                        CU_TENSOR_MAP_FLOAT_OOB_FILL_NONE);

    int blocks = (B + ROWS_PER_BLOCK - 1) / ROWS_PER_BLOCK;
    sm2_scan_kernel<<<blocks, THREADS>>>(tmap, out, B);
}